// round 11
// baseline (speedup 1.0000x reference)
#include <cuda_runtime.h>
#include <cstdint>

// Merged-pair tables (L2-resident across replays).
__device__ float H0[65536 * 8];    // (i0*256+i1) -> vec[8]           (2MB)
__device__ float H1[65536 * 64];   // (i2*256+i3) -> mat[r][s] 8x8    (16MB)
__device__ float H2[65536 * 64];   // (i4*256+i5) -> mat[r][s] 8x8    (16MB)
__device__ float H3[65536 * 8];    // (i6*256+a)  -> vec[8]           (2MB)

// ---------- P1: H0[i,j,s] = sum_t G0[0,i,t] * G1[t,j,s] ----------
__global__ void __launch_bounds__(256)
build_H0(const float* __restrict__ G0, const float* __restrict__ G1)
{
    const int i = blockIdx.x;      // 0..255
    const int j = threadIdx.x;     // 0..255
    float a[8];
#pragma unroll
    for (int t = 0; t < 8; t++) a[t] = __ldg(G0 + i * 8 + t);
    float o[8];
#pragma unroll
    for (int s = 0; s < 8; s++) o[s] = 0.f;
#pragma unroll
    for (int t = 0; t < 8; t++) {
        const float* b = G1 + (t * 256 + j) * 8;
#pragma unroll
        for (int s = 0; s < 8; s++) o[s] = fmaf(a[t], __ldg(b + s), o[s]);
    }
    float4* dst = (float4*)(H0 + (i * 256 + j) * 8);
    dst[0] = make_float4(o[0], o[1], o[2], o[3]);
    dst[1] = make_float4(o[4], o[5], o[6], o[7]);
}

// ---------- P2/P3: Hm[pair][r][s] = sum_t A[r,i,t] * Bc[t,j,s] ----------
__global__ void __launch_bounds__(256)
build_Hmid(const float* __restrict__ A, const float* __restrict__ Bc, float* __restrict__ Hm)
{
    const int gtid = blockIdx.x * 256 + threadIdx.x;   // 524288 threads
    const int pair = gtid >> 3;
    const int r    = gtid & 7;
    const int i    = pair >> 8;
    const int j    = pair & 255;
    float a[8];
#pragma unroll
    for (int t = 0; t < 8; t++) a[t] = __ldg(A + (r * 256 + i) * 8 + t);
    float o[8];
#pragma unroll
    for (int s = 0; s < 8; s++) o[s] = 0.f;
#pragma unroll
    for (int t = 0; t < 8; t++) {
        const float* b = Bc + (t * 256 + j) * 8;
#pragma unroll
        for (int s = 0; s < 8; s++) o[s] = fmaf(a[t], __ldg(b + s), o[s]);
    }
    float4* dst = (float4*)(Hm + pair * 64 + r * 8);
    dst[0] = make_float4(o[0], o[1], o[2], o[3]);
    dst[1] = make_float4(o[4], o[5], o[6], o[7]);
}

// ---------- P4: H3[(i*256+j)][r] = sum_t G6[r,i,t] * G7[t*256+j] ----------
__global__ void __launch_bounds__(256)
build_H3(const float* __restrict__ G6, const float* __restrict__ G7)
{
    const int i = blockIdx.x;
    const int j = threadIdx.x;
    float b[8];
#pragma unroll
    for (int t = 0; t < 8; t++) b[t] = __ldg(G7 + t * 256 + j);
    float o[8];
#pragma unroll
    for (int r = 0; r < 8; r++) {
        const float* a = G6 + (r * 256 + i) * 8;
        float acc = 0.f;
#pragma unroll
        for (int t = 0; t < 8; t++) acc = fmaf(__ldg(a + t), b[t], acc);
        o[r] = acc;
    }
    float4* dst = (float4*)(H3 + (i * 256 + j) * 8);
    dst[0] = make_float4(o[0], o[1], o[2], o[3]);
    dst[1] = make_float4(o[4], o[5], o[6], o[7]);
}

// ---------- Main: Q = (H0[i01] . H1[i23]) . H2[i45] . H3[i67] ----------
__global__ void __launch_bounds__(256)
tt_main(const int* __restrict__ states, const int* __restrict__ actions,
        float* __restrict__ out, int Btot)
{
    const int e = blockIdx.x * 256 + threadIdx.x;
    if (e >= Btot) return;

    const int* sp = states + e * 7;
    const int s0 = __ldg(sp), s1 = __ldg(sp + 1), s2 = __ldg(sp + 2),
              s3 = __ldg(sp + 3), s4 = __ldg(sp + 4), s5 = __ldg(sp + 5),
              s6 = __ldg(sp + 6);
    const int a  = __ldg(actions + e);

    const float4* p0 = (const float4*)(H0 + (s0 * 256 + s1) * 8);
    const float4* p1 = (const float4*)(H1 + (size_t)(s2 * 256 + s3) * 64);
    const float4* p2 = (const float4*)(H2 + (size_t)(s4 * 256 + s5) * 64);
    const float4* p3 = (const float4*)(H3 + (s6 * 256 + a) * 8);

    // Issue all loads up front (MLP=36, addresses fully independent of data).
    float4 v0a = p0[0], v0b = p0[1];
    float4 m1[16];
#pragma unroll
    for (int c = 0; c < 16; c++) m1[c] = p1[c];
    float4 m2[16];
#pragma unroll
    for (int c = 0; c < 16; c++) m2[c] = p2[c];
    float4 v3a = p3[0], v3b = p3[1];

    const float v0[8] = { v0a.x, v0a.y, v0a.z, v0a.w, v0b.x, v0b.y, v0b.z, v0b.w };

    // u = v0 x M23   (M[r][s], row r = m1[2r], m1[2r+1])
    float u[8];
    u[0] = v0[0] * m1[0].x; u[1] = v0[0] * m1[0].y;
    u[2] = v0[0] * m1[0].z; u[3] = v0[0] * m1[0].w;
    u[4] = v0[0] * m1[1].x; u[5] = v0[0] * m1[1].y;
    u[6] = v0[0] * m1[1].z; u[7] = v0[0] * m1[1].w;
#pragma unroll
    for (int r = 1; r < 8; r++) {
        const float w = v0[r];
        u[0] = fmaf(w, m1[2 * r].x, u[0]);
        u[1] = fmaf(w, m1[2 * r].y, u[1]);
        u[2] = fmaf(w, m1[2 * r].z, u[2]);
        u[3] = fmaf(w, m1[2 * r].w, u[3]);
        u[4] = fmaf(w, m1[2 * r + 1].x, u[4]);
        u[5] = fmaf(w, m1[2 * r + 1].y, u[5]);
        u[6] = fmaf(w, m1[2 * r + 1].z, u[6]);
        u[7] = fmaf(w, m1[2 * r + 1].w, u[7]);
    }

    // t = u x M45
    float t[8];
    t[0] = u[0] * m2[0].x; t[1] = u[0] * m2[0].y;
    t[2] = u[0] * m2[0].z; t[3] = u[0] * m2[0].w;
    t[4] = u[0] * m2[1].x; t[5] = u[0] * m2[1].y;
    t[6] = u[0] * m2[1].z; t[7] = u[0] * m2[1].w;
#pragma unroll
    for (int r = 1; r < 8; r++) {
        const float w = u[r];
        t[0] = fmaf(w, m2[2 * r].x, t[0]);
        t[1] = fmaf(w, m2[2 * r].y, t[1]);
        t[2] = fmaf(w, m2[2 * r].z, t[2]);
        t[3] = fmaf(w, m2[2 * r].w, t[3]);
        t[4] = fmaf(w, m2[2 * r + 1].x, t[4]);
        t[5] = fmaf(w, m2[2 * r + 1].y, t[5]);
        t[6] = fmaf(w, m2[2 * r + 1].z, t[6]);
        t[7] = fmaf(w, m2[2 * r + 1].w, t[7]);
    }

    // Q = t . v3
    float q = t[0] * v3a.x;
    q = fmaf(t[1], v3a.y, q);
    q = fmaf(t[2], v3a.z, q);
    q = fmaf(t[3], v3a.w, q);
    q = fmaf(t[4], v3b.x, q);
    q = fmaf(t[5], v3b.y, q);
    q = fmaf(t[6], v3b.z, q);
    q = fmaf(t[7], v3b.w, q);

    out[e] = q;
}

extern "C" void kernel_launch(void* const* d_in, const int* in_sizes, int n_in,
                              void* d_out, int out_size)
{
    const float* G0 = (const float*)d_in[0];
    const float* G1 = (const float*)d_in[1];
    const float* G2 = (const float*)d_in[2];
    const float* G3 = (const float*)d_in[3];
    const float* G4 = (const float*)d_in[4];
    const float* G5 = (const float*)d_in[5];
    const float* G6 = (const float*)d_in[6];
    const float* G7 = (const float*)d_in[7];
    const int* states  = (const int*)d_in[8];
    const int* actions = (const int*)d_in[9];
    const int B = in_sizes[9];

    float *h1p, *h2p;
    cudaGetSymbolAddress((void**)&h1p, H1);
    cudaGetSymbolAddress((void**)&h2p, H2);

    build_H0  <<<256, 256>>>(G0, G1);
    build_Hmid<<<2048, 256>>>(G2, G3, h1p);
    build_Hmid<<<2048, 256>>>(G4, G5, h2p);
    build_H3  <<<256, 256>>>(G6, G7);

    tt_main<<<(B + 255) / 256, 256>>>(states, actions, (float*)d_out, B);
}

// round 12
// speedup vs baseline: 1.2080x; 1.2080x over previous
#include <cuda_runtime.h>
#include <cstdint>

// Merged-pair tables (built every call; L2-resident).
__device__ float H0v[65536 * 8];    // (i0,i1) -> vec[8]                        (2MB)
__device__ float H1v[65536 * 64];   // (i2,i3) -> mat, split-half row layout    (16MB)
__device__ float H2v[65536 * 64];   // (i4,i5) -> mat, split-half row layout    (16MB)
__device__ float H3v[65536 * 8];    // (i6,a)  -> vec[8]                        (2MB)

// Split-half layout for H1/H2: float4 index slice*16 + h*8 + j  = row j, half h.
// Main kernel: lane j reads f4 (slice*16 + j) and (slice*16 + 8 + j) ->
// 8 lanes x 16B = one full 128B line per element per half.

// ---------------- Fused build kernel ----------------
__global__ void __launch_bounds__(256)
build_all(const float* __restrict__ G0, const float* __restrict__ G1,
          const float* __restrict__ G2, const float* __restrict__ G3,
          const float* __restrict__ G4, const float* __restrict__ G5,
          const float* __restrict__ G6, const float* __restrict__ G7)
{
    const int bid = blockIdx.x;
    const int tid = threadIdx.x;

    if (bid < 4096) {
        // H1 (bid<2048) / H2 sections: 524288 threads each; thread = (pair, r).
        const bool second = (bid >= 2048);
        const float* A  = second ? G4 : G2;
        const float* Bc = second ? G5 : G3;
        float* Hm       = second ? H2v : H1v;
        const int gt = (second ? bid - 2048 : bid) * 256 + tid;
        const int pair = gt >> 3;
        const int r    = gt & 7;
        const int i    = pair >> 8;
        const int jj   = pair & 255;
        const float4* Ar = (const float4*)(A + (r * 256 + i) * 8);
        float4 a0 = __ldg(Ar), a1 = __ldg(Ar + 1);
        const float a[8] = { a0.x, a0.y, a0.z, a0.w, a1.x, a1.y, a1.z, a1.w };
        float o[8];
#pragma unroll
        for (int s = 0; s < 8; s++) o[s] = 0.f;
#pragma unroll
        for (int t = 0; t < 8; t++) {
            const float4* Br = (const float4*)(Bc + (t * 256 + jj) * 8);
            float4 b0 = __ldg(Br), b1 = __ldg(Br + 1);
            const float w = a[t];
            o[0] = fmaf(w, b0.x, o[0]); o[1] = fmaf(w, b0.y, o[1]);
            o[2] = fmaf(w, b0.z, o[2]); o[3] = fmaf(w, b0.w, o[3]);
            o[4] = fmaf(w, b1.x, o[4]); o[5] = fmaf(w, b1.y, o[5]);
            o[6] = fmaf(w, b1.z, o[6]); o[7] = fmaf(w, b1.w, o[7]);
        }
        float4* Hf4 = (float4*)Hm;
        Hf4[(size_t)pair * 16 + r]     = make_float4(o[0], o[1], o[2], o[3]);
        Hf4[(size_t)pair * 16 + 8 + r] = make_float4(o[4], o[5], o[6], o[7]);
    } else if (bid < 4352) {
        // H0: 65536 threads; thread = pair (i,j). o[s] = sum_t G0[i,t]*G1[t,j,s]
        const int pair = (bid - 4096) * 256 + tid;
        const int i = pair >> 8, jj = pair & 255;
        const float4* Ar = (const float4*)(G0 + i * 8);
        float4 a0 = __ldg(Ar), a1 = __ldg(Ar + 1);
        const float a[8] = { a0.x, a0.y, a0.z, a0.w, a1.x, a1.y, a1.z, a1.w };
        float o[8];
#pragma unroll
        for (int s = 0; s < 8; s++) o[s] = 0.f;
#pragma unroll
        for (int t = 0; t < 8; t++) {
            const float4* Br = (const float4*)(G1 + (t * 256 + jj) * 8);
            float4 b0 = __ldg(Br), b1 = __ldg(Br + 1);
            const float w = a[t];
            o[0] = fmaf(w, b0.x, o[0]); o[1] = fmaf(w, b0.y, o[1]);
            o[2] = fmaf(w, b0.z, o[2]); o[3] = fmaf(w, b0.w, o[3]);
            o[4] = fmaf(w, b1.x, o[4]); o[5] = fmaf(w, b1.y, o[5]);
            o[6] = fmaf(w, b1.z, o[6]); o[7] = fmaf(w, b1.w, o[7]);
        }
        float4* dst = (float4*)(H0v + (size_t)pair * 8);
        dst[0] = make_float4(o[0], o[1], o[2], o[3]);
        dst[1] = make_float4(o[4], o[5], o[6], o[7]);
    } else {
        // H3: 65536 threads; thread = pair (i,j). o[r] = sum_t G6[r,i,t]*G7[t*256+j]
        const int pair = (bid - 4352) * 256 + tid;
        const int i = pair >> 8, jj = pair & 255;
        float b[8];
#pragma unroll
        for (int t = 0; t < 8; t++) b[t] = __ldg(G7 + t * 256 + jj);
        float o[8];
#pragma unroll
        for (int r = 0; r < 8; r++) {
            const float4* Ar = (const float4*)(G6 + (r * 256 + i) * 8);
            float4 a0 = __ldg(Ar), a1 = __ldg(Ar + 1);
            o[r] = a0.x * b[0] + a0.y * b[1] + a0.z * b[2] + a0.w * b[3]
                 + a1.x * b[4] + a1.y * b[5] + a1.z * b[6] + a1.w * b[7];
        }
        float4* dst = (float4*)(H3v + (size_t)pair * 8);
        dst[0] = make_float4(o[0], o[1], o[2], o[3]);
        dst[1] = make_float4(o[4], o[5], o[6], o[7]);
    }
}

// One merged stage: lane j holds scalar v_j and row j of M (lo|hi).
// Returns u_j = sum_r v_r * M[r][j] via xor-4/2/1 reduce-scatter.
__device__ __forceinline__ float matstage(float v, float4 lo, float4 hi, int j)
{
    const unsigned F = 0xffffffffu;
    float p0 = v * lo.x, p1 = v * lo.y, p2 = v * lo.z, p3 = v * lo.w;
    float p4 = v * hi.x, p5 = v * hi.y, p6 = v * hi.z, p7 = v * hi.w;
    const bool b4 = (j & 4) != 0;
    float k0 = b4 ? p4 : p0, k1 = b4 ? p5 : p1, k2 = b4 ? p6 : p2, k3 = b4 ? p7 : p3;
    float s0 = b4 ? p0 : p4, s1 = b4 ? p1 : p5, s2 = b4 ? p2 : p6, s3 = b4 ? p3 : p7;
    k0 += __shfl_xor_sync(F, s0, 4);
    k1 += __shfl_xor_sync(F, s1, 4);
    k2 += __shfl_xor_sync(F, s2, 4);
    k3 += __shfl_xor_sync(F, s3, 4);
    const bool b2 = (j & 2) != 0;
    float q0 = b2 ? k2 : k0, q1 = b2 ? k3 : k1;
    float t0 = b2 ? k0 : k2, t1 = b2 ? k1 : k3;
    q0 += __shfl_xor_sync(F, t0, 2);
    q1 += __shfl_xor_sync(F, t1, 2);
    const bool b1 = (j & 1) != 0;
    float z = b1 ? q1 : q0, y = b1 ? q0 : q1;
    z += __shfl_xor_sync(F, y, 1);
    return z;     // = u_j
}

// ---------------- Main: 8 lanes per element ----------------
__global__ void __launch_bounds__(512)
tt_main(const int* __restrict__ states, const int* __restrict__ actions,
        float* __restrict__ out, int Btot)
{
    const unsigned F = 0xffffffffu;
    const int tid  = threadIdx.x;
    const int gw   = (blockIdx.x * 512 + tid) >> 5;   // global warp: 4 elements
    const int lane = tid & 31;
    const int g    = lane >> 3;                       // element slot in warp
    const int j    = lane & 7;                        // rank lane

    // Coalesced index fetch for the warp's 4 elements.
    int raw = 0;
    if (lane < 28) {
        long idx = (long)gw * 28 + lane;
        if (idx < (long)Btot * 7) raw = __ldg(states + idx);
    }
    int act = 0;
    if (lane < 4) {
        int idx = gw * 4 + lane;
        if (idx < Btot) act = __ldg(actions + idx);
    }

    const int s0 = __shfl_sync(F, raw, g * 7 + 0);
    const int s1 = __shfl_sync(F, raw, g * 7 + 1);
    const int s2 = __shfl_sync(F, raw, g * 7 + 2);
    const int s3 = __shfl_sync(F, raw, g * 7 + 3);
    const int s4 = __shfl_sync(F, raw, g * 7 + 4);
    const int s5 = __shfl_sync(F, raw, g * 7 + 5);
    const int s6 = __shfl_sync(F, raw, g * 7 + 6);
    const int aa = __shfl_sync(F, act, g);

    // v0_j
    float v = __ldg(H0v + (size_t)(s0 * 256 + s1) * 8 + j);

    // Stage 1: M23 (lane j reads its own row -> full-line coalesced)
    {
        const float4* P = (const float4*)H1v + (size_t)(s2 * 256 + s3) * 16;
        float4 lo = __ldg(P + j);
        float4 hi = __ldg(P + 8 + j);
        v = matstage(v, lo, hi, j);
    }
    // Stage 2: M45
    {
        const float4* P = (const float4*)H2v + (size_t)(s4 * 256 + s5) * 16;
        float4 lo = __ldg(P + j);
        float4 hi = __ldg(P + 8 + j);
        v = matstage(v, lo, hi, j);
    }
    // Final dot with H3 + butterfly sum.
    float h3 = __ldg(H3v + (size_t)(s6 * 256 + aa) * 8 + j);
    float q = v * h3;
    q += __shfl_xor_sync(F, q, 1);
    q += __shfl_xor_sync(F, q, 2);
    q += __shfl_xor_sync(F, q, 4);

    const int e = gw * 4 + g;
    if (j == 0 && e < Btot) out[e] = q;
}

extern "C" void kernel_launch(void* const* d_in, const int* in_sizes, int n_in,
                              void* d_out, int out_size)
{
    const float* G0 = (const float*)d_in[0];
    const float* G1 = (const float*)d_in[1];
    const float* G2 = (const float*)d_in[2];
    const float* G3 = (const float*)d_in[3];
    const float* G4 = (const float*)d_in[4];
    const float* G5 = (const float*)d_in[5];
    const float* G6 = (const float*)d_in[6];
    const float* G7 = (const float*)d_in[7];
    const int* states  = (const int*)d_in[8];
    const int* actions = (const int*)d_in[9];
    const int B = in_sizes[9];

    build_all<<<4608, 256>>>(G0, G1, G2, G3, G4, G5, G6, G7);

    // 4 elements per warp, 16 warps per block -> 64 elements per block.
    const int grid = (B + 63) / 64;
    tt_main<<<grid, 512>>>(states, actions, (float*)d_out, B);
}

// round 14
// speedup vs baseline: 2.0629x; 1.7077x over previous
#include <cuda_runtime.h>
#include <cstdint>

// Merged-pair tables (rebuilt every call; L2-resident).
// H1/H2 layout (COLUMN-major, split-half): float4 index pair*16 + h*8 + s
//   = column s of M, rows 4h..4h+3.  Main: lane j reads cols -> 128B line/group.
__device__ float H0v[65536 * 8];    // (i0,i1) -> vec[8]   (2MB)
__device__ float H1v[65536 * 64];   // (i2,i3) -> mat^T    (16MB)
__device__ float H2v[65536 * 64];   // (i4,i5) -> mat^T    (16MB)
__device__ float H3v[65536 * 8];    // (i6,a)  -> vec[8]   (2MB)

// ---------------- Fused build kernel (1536 blocks x 256) ----------------
__global__ void __launch_bounds__(256)
build_all(const float* __restrict__ G0, const float* __restrict__ G1,
          const float* __restrict__ G2, const float* __restrict__ G3,
          const float* __restrict__ G4, const float* __restrict__ G5,
          const float* __restrict__ G6, const float* __restrict__ G7)
{
    const int bid = blockIdx.x;
    const int tid = threadIdx.x;

    if (bid < 1024) {
        // H1 (bid<512) / H2: 2 threads per pair, each a 4x8 half, col-major.
        const bool second = (bid >= 512);
        const float* A  = second ? G4 : G2;
        const float* Bc = second ? G5 : G3;
        float* Hm       = second ? H2v : H1v;
        const int gt   = (second ? bid - 512 : bid) * 256 + tid;
        const int pair = gt >> 1;
        const int rh   = gt & 1;          // row-half: rows 4rh..4rh+3
        const int i    = pair >> 8;
        const int j    = pair & 255;

        // a[rr][t] = A[(4rh+rr)*256+i][t]
        float a[4][8];
#pragma unroll
        for (int rr = 0; rr < 4; rr++) {
            const float4* Ar = (const float4*)(A + (((rh * 4 + rr) * 256 + i) * 8));
            float4 a0 = __ldg(Ar), a1 = __ldg(Ar + 1);
            a[rr][0] = a0.x; a[rr][1] = a0.y; a[rr][2] = a0.z; a[rr][3] = a0.w;
            a[rr][4] = a1.x; a[rr][5] = a1.y; a[rr][6] = a1.z; a[rr][7] = a1.w;
        }
        // uc[s] = column s, rows 4rh..4rh+3
        float4 uc[8];
#pragma unroll
        for (int s = 0; s < 8; s++) uc[s] = make_float4(0.f, 0.f, 0.f, 0.f);
#pragma unroll
        for (int t = 0; t < 8; t++) {
            const float4* Br = (const float4*)(Bc + ((t * 256 + j) * 8));
            float4 b0 = __ldg(Br), b1 = __ldg(Br + 1);
            const float b[8] = { b0.x, b0.y, b0.z, b0.w, b1.x, b1.y, b1.z, b1.w };
#pragma unroll
            for (int s = 0; s < 8; s++) {
                uc[s].x = fmaf(a[0][t], b[s], uc[s].x);
                uc[s].y = fmaf(a[1][t], b[s], uc[s].y);
                uc[s].z = fmaf(a[2][t], b[s], uc[s].z);
                uc[s].w = fmaf(a[3][t], b[s], uc[s].w);
            }
        }
        // Contiguous 128B write: f4 idx pair*16 + rh*8 + s
        float4* dst = (float4*)Hm + (size_t)pair * 16 + rh * 8;
#pragma unroll
        for (int s = 0; s < 8; s++) dst[s] = uc[s];
    } else if (bid < 1280) {
        // H0: thread per pair. o[s] = sum_t G0[i,t] * G1[t,j,s]
        const int pair = (bid - 1024) * 256 + tid;
        const int i = pair >> 8, j = pair & 255;
        const float4* Ar = (const float4*)(G0 + i * 8);
        float4 a0 = __ldg(Ar), a1 = __ldg(Ar + 1);
        const float a[8] = { a0.x, a0.y, a0.z, a0.w, a1.x, a1.y, a1.z, a1.w };
        float o[8];
#pragma unroll
        for (int s = 0; s < 8; s++) o[s] = 0.f;
#pragma unroll
        for (int t = 0; t < 8; t++) {
            const float4* Br = (const float4*)(G1 + (t * 256 + j) * 8);
            float4 b0 = __ldg(Br), b1 = __ldg(Br + 1);
            const float w = a[t];
            o[0] = fmaf(w, b0.x, o[0]); o[1] = fmaf(w, b0.y, o[1]);
            o[2] = fmaf(w, b0.z, o[2]); o[3] = fmaf(w, b0.w, o[3]);
            o[4] = fmaf(w, b1.x, o[4]); o[5] = fmaf(w, b1.y, o[5]);
            o[6] = fmaf(w, b1.z, o[6]); o[7] = fmaf(w, b1.w, o[7]);
        }
        float4* dst = (float4*)(H0v + (size_t)pair * 8);
        dst[0] = make_float4(o[0], o[1], o[2], o[3]);
        dst[1] = make_float4(o[4], o[5], o[6], o[7]);
    } else {
        // H3: thread per pair. o[r] = sum_t G6[r,i,t] * G7[t*256+j]
        const int pair = (bid - 1280) * 256 + tid;
        const int i = pair >> 8, j = pair & 255;
        float b[8];
#pragma unroll
        for (int t = 0; t < 8; t++) b[t] = __ldg(G7 + t * 256 + j);
        float o[8];
#pragma unroll
        for (int r = 0; r < 8; r++) {
            const float4* Ar = (const float4*)(G6 + (r * 256 + i) * 8);
            float4 a0 = __ldg(Ar), a1 = __ldg(Ar + 1);
            o[r] = a0.x * b[0] + a0.y * b[1] + a0.z * b[2] + a0.w * b[3]
                 + a1.x * b[4] + a1.y * b[5] + a1.z * b[6] + a1.w * b[7];
        }
        float4* dst = (float4*)(H3v + (size_t)pair * 8);
        dst[0] = make_float4(o[0], o[1], o[2], o[3]);
        dst[1] = make_float4(o[4], o[5], o[6], o[7]);
    }
}

// ---------------- Main: 8 lanes per element, column scheme ----------------
__global__ void __launch_bounds__(512)
tt_main(const int* __restrict__ states, const int* __restrict__ actions,
        float* __restrict__ out, int Btot)
{
    const unsigned F = 0xffffffffu;
    const int tid  = threadIdx.x;
    const int gw   = (blockIdx.x * 512 + tid) >> 5;   // global warp: 4 elements
    const int lane = tid & 31;
    const int g    = lane >> 3;                       // element slot in warp
    const int j    = lane & 7;                        // rank lane
    const int gb   = g * 8;                           // group base lane

    // Coalesced index fetch for the warp's 4 elements.
    int raw = 0;
    if (lane < 28) {
        long idx = (long)gw * 28 + lane;
        if (idx < (long)Btot * 7) raw = __ldg(states + idx);
    }
    int act = 0;
    if (lane < 4) {
        int idx = gw * 4 + lane;
        if (idx < Btot) act = __ldg(actions + idx);
    }

    const int s0 = __shfl_sync(F, raw, g * 7 + 0);
    const int s1 = __shfl_sync(F, raw, g * 7 + 1);
    const int s2 = __shfl_sync(F, raw, g * 7 + 2);
    const int s3 = __shfl_sync(F, raw, g * 7 + 3);
    const int s4 = __shfl_sync(F, raw, g * 7 + 4);
    const int s5 = __shfl_sync(F, raw, g * 7 + 5);
    const int s6 = __shfl_sync(F, raw, g * 7 + 6);
    const int aa = __shfl_sync(F, act, g);

    // v_j from H0
    float v = __ldg(H0v + (size_t)(s0 * 256 + s1) * 8 + j);

    // Stage 1: lane j loads COLUMN j of M23; u_j = sum_r v_r * M[r][j]
    {
        const float4* P = (const float4*)H1v + (size_t)(s2 * 256 + s3) * 16;
        float4 lo = __ldg(P + j);        // rows 0-3 of col j
        float4 hi = __ldg(P + 8 + j);    // rows 4-7 of col j
        float u;
        u = __shfl_sync(F, v, gb + 0) * lo.x;
        u = fmaf(__shfl_sync(F, v, gb + 1), lo.y, u);
        u = fmaf(__shfl_sync(F, v, gb + 2), lo.z, u);
        u = fmaf(__shfl_sync(F, v, gb + 3), lo.w, u);
        u = fmaf(__shfl_sync(F, v, gb + 4), hi.x, u);
        u = fmaf(__shfl_sync(F, v, gb + 5), hi.y, u);
        u = fmaf(__shfl_sync(F, v, gb + 6), hi.z, u);
        u = fmaf(__shfl_sync(F, v, gb + 7), hi.w, u);
        v = u;
    }
    // Stage 2: M45
    {
        const float4* P = (const float4*)H2v + (size_t)(s4 * 256 + s5) * 16;
        float4 lo = __ldg(P + j);
        float4 hi = __ldg(P + 8 + j);
        float u;
        u = __shfl_sync(F, v, gb + 0) * lo.x;
        u = fmaf(__shfl_sync(F, v, gb + 1), lo.y, u);
        u = fmaf(__shfl_sync(F, v, gb + 2), lo.z, u);
        u = fmaf(__shfl_sync(F, v, gb + 3), lo.w, u);
        u = fmaf(__shfl_sync(F, v, gb + 4), hi.x, u);
        u = fmaf(__shfl_sync(F, v, gb + 5), hi.y, u);
        u = fmaf(__shfl_sync(F, v, gb + 6), hi.z, u);
        u = fmaf(__shfl_sync(F, v, gb + 7), hi.w, u);
        v = u;
    }
    // Final dot with H3 + butterfly sum within the 8-lane group.
    float h3 = __ldg(H3v + (size_t)(s6 * 256 + aa) * 8 + j);
    float q = v * h3;
    q += __shfl_xor_sync(F, q, 1);
    q += __shfl_xor_sync(F, q, 2);
    q += __shfl_xor_sync(F, q, 4);

    const int e = gw * 4 + g;
    if (j == 0 && e < Btot) out[e] = q;
}

extern "C" void kernel_launch(void* const* d_in, const int* in_sizes, int n_in,
                              void* d_out, int out_size)
{
    const float* G0 = (const float*)d_in[0];
    const float* G1 = (const float*)d_in[1];
    const float* G2 = (const float*)d_in[2];
    const float* G3 = (const float*)d_in[3];
    const float* G4 = (const float*)d_in[4];
    const float* G5 = (const float*)d_in[5];
    const float* G6 = (const float*)d_in[6];
    const float* G7 = (const float*)d_in[7];
    const int* states  = (const int*)d_in[8];
    const int* actions = (const int*)d_in[9];
    const int B = in_sizes[9];

    build_all<<<1536, 256>>>(G0, G1, G2, G3, G4, G5, G6, G7);

    // 4 elements per warp, 16 warps per block -> 64 elements per block.
    const int grid = (B + 63) / 64;
    tt_main<<<grid, 512>>>(states, actions, (float*)d_out, B);
}

// round 15
// speedup vs baseline: 2.0798x; 1.0082x over previous
#include <cuda_runtime.h>
#include <cstdint>

// Merged-pair tables (rebuilt every call; L2-resident).
// H1/H2 layout (COLUMN-major, split-half): float4 index pair*16 + h*8 + s
//   = column s of M, rows 4h..4h+3.  Main: lane j reads cols -> 128B line/group.
__device__ float H0v[65536 * 8];    // (i0,i1) -> vec[8]   (2MB)
__device__ float H1v[65536 * 64];   // (i2,i3) -> mat^T    (16MB)
__device__ float H2v[65536 * 64];   // (i4,i5) -> mat^T    (16MB)
__device__ float H3v[65536 * 8];    // (i6,a)  -> vec[8]   (2MB)

// ---------------- Fused build kernel (3072 blocks x 128) ----------------
__global__ void __launch_bounds__(128)
build_all(const float* __restrict__ G0, const float* __restrict__ G1,
          const float* __restrict__ G2, const float* __restrict__ G3,
          const float* __restrict__ G4, const float* __restrict__ G5,
          const float* __restrict__ G6, const float* __restrict__ G7)
{
    const int bid = blockIdx.x;
    const int tid = threadIdx.x;

    if (bid < 2048) {
        // H1 (bid<1024) / H2: 2 threads per pair, each a 4x8 half, col-major.
        const bool second = (bid >= 1024);
        const float* A  = second ? G4 : G2;
        const float* Bc = second ? G5 : G3;
        float* Hm       = second ? H2v : H1v;
        const int gt   = (second ? bid - 1024 : bid) * 128 + tid;
        const int pair = gt >> 1;
        const int rh   = gt & 1;          // row-half: rows 4rh..4rh+3
        const int i    = pair >> 8;
        const int j    = pair & 255;

        // Batch ALL loads first: 16 B-f4 + 8 A-f4 = MLP 24.
        float4 b[16];
#pragma unroll
        for (int t = 0; t < 8; t++) {
            const float4* Br = (const float4*)(Bc + ((t * 256 + j) * 8));
            b[2 * t]     = __ldg(Br);
            b[2 * t + 1] = __ldg(Br + 1);
        }
        float4 av[8];
#pragma unroll
        for (int rr = 0; rr < 4; rr++) {
            const float4* Ar = (const float4*)(A + (((rh * 4 + rr) * 256 + i) * 8));
            av[2 * rr]     = __ldg(Ar);
            av[2 * rr + 1] = __ldg(Ar + 1);
        }
        float a[4][8];
#pragma unroll
        for (int rr = 0; rr < 4; rr++) {
            a[rr][0] = av[2 * rr].x;     a[rr][1] = av[2 * rr].y;
            a[rr][2] = av[2 * rr].z;     a[rr][3] = av[2 * rr].w;
            a[rr][4] = av[2 * rr + 1].x; a[rr][5] = av[2 * rr + 1].y;
            a[rr][6] = av[2 * rr + 1].z; a[rr][7] = av[2 * rr + 1].w;
        }
        // uc[s] = column s, rows 4rh..4rh+3
        float4 uc[8];
#pragma unroll
        for (int s = 0; s < 8; s++) uc[s] = make_float4(0.f, 0.f, 0.f, 0.f);
#pragma unroll
        for (int t = 0; t < 8; t++) {
            const float bb[8] = { b[2 * t].x, b[2 * t].y, b[2 * t].z, b[2 * t].w,
                                  b[2 * t + 1].x, b[2 * t + 1].y, b[2 * t + 1].z, b[2 * t + 1].w };
#pragma unroll
            for (int s = 0; s < 8; s++) {
                uc[s].x = fmaf(a[0][t], bb[s], uc[s].x);
                uc[s].y = fmaf(a[1][t], bb[s], uc[s].y);
                uc[s].z = fmaf(a[2][t], bb[s], uc[s].z);
                uc[s].w = fmaf(a[3][t], bb[s], uc[s].w);
            }
        }
        // Contiguous 128B write: f4 idx pair*16 + rh*8 + s
        float4* dst = (float4*)Hm + (size_t)pair * 16 + rh * 8;
#pragma unroll
        for (int s = 0; s < 8; s++) dst[s] = uc[s];
    } else if (bid < 2560) {
        // H0: thread per pair. o[s] = sum_t G0[i,t] * G1[t,j,s]
        const int pair = (bid - 2048) * 128 + tid;
        const int i = pair >> 8, j = pair & 255;
        float4 b[16];
#pragma unroll
        for (int t = 0; t < 8; t++) {
            const float4* Br = (const float4*)(G1 + (t * 256 + j) * 8);
            b[2 * t]     = __ldg(Br);
            b[2 * t + 1] = __ldg(Br + 1);
        }
        const float4* Ar = (const float4*)(G0 + i * 8);
        float4 a0 = __ldg(Ar), a1 = __ldg(Ar + 1);
        const float a[8] = { a0.x, a0.y, a0.z, a0.w, a1.x, a1.y, a1.z, a1.w };
        float o[8];
#pragma unroll
        for (int s = 0; s < 8; s++) o[s] = 0.f;
#pragma unroll
        for (int t = 0; t < 8; t++) {
            const float w = a[t];
            o[0] = fmaf(w, b[2 * t].x, o[0]);     o[1] = fmaf(w, b[2 * t].y, o[1]);
            o[2] = fmaf(w, b[2 * t].z, o[2]);     o[3] = fmaf(w, b[2 * t].w, o[3]);
            o[4] = fmaf(w, b[2 * t + 1].x, o[4]); o[5] = fmaf(w, b[2 * t + 1].y, o[5]);
            o[6] = fmaf(w, b[2 * t + 1].z, o[6]); o[7] = fmaf(w, b[2 * t + 1].w, o[7]);
        }
        float4* dst = (float4*)(H0v + (size_t)pair * 8);
        dst[0] = make_float4(o[0], o[1], o[2], o[3]);
        dst[1] = make_float4(o[4], o[5], o[6], o[7]);
    } else {
        // H3: thread per pair. o[r] = sum_t G6[r,i,t] * G7[t*256+j]
        const int pair = (bid - 2560) * 128 + tid;
        const int i = pair >> 8, j = pair & 255;
        float b[8];
#pragma unroll
        for (int t = 0; t < 8; t++) b[t] = __ldg(G7 + t * 256 + j);
        float4 av[16];
#pragma unroll
        for (int r = 0; r < 8; r++) {
            const float4* Ar = (const float4*)(G6 + (r * 256 + i) * 8);
            av[2 * r]     = __ldg(Ar);
            av[2 * r + 1] = __ldg(Ar + 1);
        }
        float o[8];
#pragma unroll
        for (int r = 0; r < 8; r++) {
            o[r] = av[2 * r].x * b[0] + av[2 * r].y * b[1]
                 + av[2 * r].z * b[2] + av[2 * r].w * b[3]
                 + av[2 * r + 1].x * b[4] + av[2 * r + 1].y * b[5]
                 + av[2 * r + 1].z * b[6] + av[2 * r + 1].w * b[7];
        }
        float4* dst = (float4*)(H3v + (size_t)pair * 8);
        dst[0] = make_float4(o[0], o[1], o[2], o[3]);
        dst[1] = make_float4(o[4], o[5], o[6], o[7]);
    }
}

// ---------------- Main: 8 lanes per element, column scheme ----------------
__global__ void __launch_bounds__(512)
tt_main(const int* __restrict__ states, const int* __restrict__ actions,
        float* __restrict__ out, int Btot)
{
    const unsigned F = 0xffffffffu;
    const int tid  = threadIdx.x;
    const int gw   = (blockIdx.x * 512 + tid) >> 5;   // global warp: 4 elements
    const int lane = tid & 31;
    const int g    = lane >> 3;                       // element slot in warp
    const int j    = lane & 7;                        // rank lane
    const int gb   = g * 8;                           // group base lane

    // Coalesced index fetch for the warp's 4 elements.
    int raw = 0;
    if (lane < 28) {
        long idx = (long)gw * 28 + lane;
        if (idx < (long)Btot * 7) raw = __ldg(states + idx);
    }
    int act = 0;
    if (lane < 4) {
        int idx = gw * 4 + lane;
        if (idx < Btot) act = __ldg(actions + idx);
    }

    const int s0 = __shfl_sync(F, raw, g * 7 + 0);
    const int s1 = __shfl_sync(F, raw, g * 7 + 1);
    const int s2 = __shfl_sync(F, raw, g * 7 + 2);
    const int s3 = __shfl_sync(F, raw, g * 7 + 3);
    const int s4 = __shfl_sync(F, raw, g * 7 + 4);
    const int s5 = __shfl_sync(F, raw, g * 7 + 5);
    const int s6 = __shfl_sync(F, raw, g * 7 + 6);
    const int aa = __shfl_sync(F, act, g);

    // Issue ALL table loads up front (addresses independent of any compute).
    const float4* P1 = (const float4*)H1v + (size_t)(s2 * 256 + s3) * 16;
    const float4* P2 = (const float4*)H2v + (size_t)(s4 * 256 + s5) * 16;
    float  v   = __ldg(H0v + (size_t)(s0 * 256 + s1) * 8 + j);
    float4 lo1 = __ldg(P1 + j);
    float4 hi1 = __ldg(P1 + 8 + j);
    float4 lo2 = __ldg(P2 + j);
    float4 hi2 = __ldg(P2 + 8 + j);
    float  h3  = __ldg(H3v + (size_t)(s6 * 256 + aa) * 8 + j);

    // Stage 1: u_j = sum_r v_r * M23[r][j]   (lane j holds col j)
    {
        float u;
        u = __shfl_sync(F, v, gb + 0) * lo1.x;
        u = fmaf(__shfl_sync(F, v, gb + 1), lo1.y, u);
        u = fmaf(__shfl_sync(F, v, gb + 2), lo1.z, u);
        u = fmaf(__shfl_sync(F, v, gb + 3), lo1.w, u);
        u = fmaf(__shfl_sync(F, v, gb + 4), hi1.x, u);
        u = fmaf(__shfl_sync(F, v, gb + 5), hi1.y, u);
        u = fmaf(__shfl_sync(F, v, gb + 6), hi1.z, u);
        u = fmaf(__shfl_sync(F, v, gb + 7), hi1.w, u);
        v = u;
    }
    // Stage 2: M45
    {
        float u;
        u = __shfl_sync(F, v, gb + 0) * lo2.x;
        u = fmaf(__shfl_sync(F, v, gb + 1), lo2.y, u);
        u = fmaf(__shfl_sync(F, v, gb + 2), lo2.z, u);
        u = fmaf(__shfl_sync(F, v, gb + 3), lo2.w, u);
        u = fmaf(__shfl_sync(F, v, gb + 4), hi2.x, u);
        u = fmaf(__shfl_sync(F, v, gb + 5), hi2.y, u);
        u = fmaf(__shfl_sync(F, v, gb + 6), hi2.z, u);
        u = fmaf(__shfl_sync(F, v, gb + 7), hi2.w, u);
        v = u;
    }
    // Final dot with H3 + butterfly sum within the 8-lane group.
    float q = v * h3;
    q += __shfl_xor_sync(F, q, 1);
    q += __shfl_xor_sync(F, q, 2);
    q += __shfl_xor_sync(F, q, 4);

    const int e = gw * 4 + g;
    if (j == 0 && e < Btot) out[e] = q;
}

extern "C" void kernel_launch(void* const* d_in, const int* in_sizes, int n_in,
                              void* d_out, int out_size)
{
    const float* G0 = (const float*)d_in[0];
    const float* G1 = (const float*)d_in[1];
    const float* G2 = (const float*)d_in[2];
    const float* G3 = (const float*)d_in[3];
    const float* G4 = (const float*)d_in[4];
    const float* G5 = (const float*)d_in[5];
    const float* G6 = (const float*)d_in[6];
    const float* G7 = (const float*)d_in[7];
    const int* states  = (const int*)d_in[8];
    const int* actions = (const int*)d_in[9];
    const int B = in_sizes[9];

    build_all<<<3072, 128>>>(G0, G1, G2, G3, G4, G5, G6, G7);

    // 4 elements per warp, 16 warps per block -> 64 elements per block.
    const int grid = (B + 63) / 64;
    tt_main<<<grid, 512>>>(states, actions, (float*)d_out, B);
}